// round 17
// baseline (speedup 1.0000x reference)
#include <cuda_runtime.h>
#include <cuda_bf16.h>
#include <cuda_fp8.h>
#include <stdint.h>
#include <math.h>

#define D       256
#define MAXB    8192
#define NCROPS  10

// FP8 GEMM tiling: 128x128 CTA tile, 4 K-chunks of 64 elems (64 B/row),
// ALL chunks resident in smem (no buffer reuse).
#define RSTRIDE 80                    // smem row stride bytes (64 data + 16 pad)
#define TILEB   (128 * RSTRIDE)       // 10240 B per operand per chunk
#define CHUNKB  (2 * TILEB)           // 20480 B (A + B)
#define SMEM_SZ (4 * CHUNKB)          // 81920 B

// ---- scratch (device globals; allocation is forbidden) ---------------------
__device__ __align__(16) uint8_t g_x8[MAXB * D];         // normalized x, e4m3 (2 MB)
__device__ float                 g_norm[MAXB];           // max(||x_i||, eps)
__device__ unsigned long long    g_best[MAXB];           // (ordered_fp32<<32)|argmax idx

__device__ __forceinline__ unsigned int ordered_fp(float f) {
    unsigned int u = __float_as_uint(f);
    return (u & 0x80000000u) ? ~u : (u | 0x80000000u);
}
__device__ __forceinline__ uint32_t smem_u32(const void* p) {
    uint32_t a;
    asm("{ .reg .u64 t; cvta.to.shared.u64 t, %1; cvt.u32.u64 %0, t; }" : "=r"(a) : "l"(p));
    return a;
}
__device__ __forceinline__ void cp16(uint32_t dst, const void* src) {
    asm volatile("cp.async.cg.shared.global [%0], [%1], 16;" :: "r"(dst), "l"(src));
}
__device__ __forceinline__ uint16_t fp8x2(float hi, float lo) {  // low byte = lo
    uint16_t h;
    asm("cvt.rn.satfinite.e4m3x2.f32 %0, %1, %2;" : "=h"(h) : "f"(hi), "f"(lo));
    return h;
}

// ---------------------------------------------------------------------------
// Kernel 1: warp-per-row L2-normalize -> e4m3. 2x float4 loads, 1x uint2 store.
// ---------------------------------------------------------------------------
__global__ void koleo_normalize(const float4* __restrict__ s, float* __restrict__ out) {
    int warp = threadIdx.x >> 5, lane = threadIdx.x & 31;
    int row  = blockIdx.x * 8 + warp;
    float4 a = s[(size_t)row * 64 + lane * 2];
    float4 b = s[(size_t)row * 64 + lane * 2 + 1];
    float ss = a.x*a.x + a.y*a.y + a.z*a.z + a.w*a.w
             + b.x*b.x + b.y*b.y + b.z*b.z + b.w*b.w;
    #pragma unroll
    for (int o = 16; o; o >>= 1) ss += __shfl_xor_sync(0xffffffffu, ss, o);
    float nrm = fmaxf(sqrtf(ss), 1e-8f);
    float inv = 1.0f / nrm;
    if (lane == 0) {
        g_norm[row] = nrm;
        g_best[row] = 0ull;
        if (row == 0) out[0] = 0.f;
    }
    uint16_t h0 = fp8x2(a.y * inv, a.x * inv);
    uint16_t h1 = fp8x2(a.w * inv, a.z * inv);
    uint16_t h2 = fp8x2(b.y * inv, b.x * inv);
    uint16_t h3 = fp8x2(b.w * inv, b.z * inv);
    uint2 pk;
    pk.x = (uint32_t)h0 | ((uint32_t)h1 << 16);
    pk.y = (uint32_t)h2 | ((uint32_t)h3 << 16);
    *(uint2*)(g_x8 + (size_t)row * D + lane * 8) = pk;
}

// ---------------------------------------------------------------------------
// Kernel 2: symmetric fused x@x^T argmax (upper-triangle 128x128 tiles only).
// e4m3 mma.sync.m16n8k32, all K resident via cp.async, ldmatrix.x4 feeds.
// ---------------------------------------------------------------------------
__global__ void __launch_bounds__(256, 2) koleo_gemm_argmax(int Bn) {
    extern __shared__ __align__(16) char smem[];
    const uint32_t sb = smem_u32(smem);

    // triangular decode: blockIdx.x -> (bm <= bn)
    int i = blockIdx.x;
    int r = (int)((sqrtf(8.0f * (float)i + 1.0f) - 1.0f) * 0.5f);
    while ((r + 1) * (r + 2) / 2 <= i) r++;
    while (r * (r + 1) / 2 > i) r--;
    const int bm = i - r * (r + 1) / 2;
    const int bn = r;
    const int rowA = bm * 128, rowB = bn * 128;

    const int t    = threadIdx.x;
    const int lane = t & 31, warp = t >> 5;
    const int wm = warp & 3, wn = warp >> 2;          // 4x2 warp grid
    const int m0 = wm * 32,  n0 = wn * 64;
    const int qr = lane >> 2, qc = lane & 3;

    // per-lane ldmatrix row / k-offset decomposition (byte-identical to bf16 case)
    const int aRow  = m0 + ((lane >> 3) & 1) * 8 + (lane & 7);
    const int aKoff = (lane >> 4) * 16;
    const int bRow  = n0 + (lane >> 4) * 8 + (lane & 7);
    const int bKoff = ((lane >> 3) & 1) * 16;

    // cp.async addressing: per chunk per tile 128 rows x 64B = 512 x 16B ops;
    // thread handles rows {t>>2, t>>2+64}, 16B col t&3.
    const char* gA_t = (const char*)g_x8 + (size_t)rowA * D + (t >> 2) * 256 + (t & 3) * 16;
    const char* gB_t = (const char*)g_x8 + (size_t)rowB * D + (t >> 2) * 256 + (t & 3) * 16;
    const uint32_t dOff = (uint32_t)((t >> 2) * RSTRIDE + (t & 3) * 16);

    float acc[2][8][4];
    #pragma unroll
    for (int mf = 0; mf < 2; mf++)
        #pragma unroll
        for (int nf = 0; nf < 8; nf++)
            #pragma unroll
            for (int e = 0; e < 4; e++) acc[mf][nf][e] = 0.f;

    // ---- prefetch ALL 4 chunks (one commit group each) ----
    #pragma unroll
    for (int kc = 0; kc < 4; kc++) {
        uint32_t base = sb + kc * CHUNKB;
        #pragma unroll
        for (int v = 0; v < 2; v++) {
            cp16(base + dOff + v * (64 * RSTRIDE),         gA_t + kc * 64 + v * (size_t)(64 * 256));
            cp16(base + dOff + v * (64 * RSTRIDE) + TILEB, gB_t + kc * 64 + v * (size_t)(64 * 256));
        }
        asm volatile("cp.async.commit_group;" ::: "memory");
    }

#define COMPUTE_CHUNK(KC)                                                         \
    {                                                                             \
        const uint32_t baseA = sb + (KC) * CHUNKB;                                \
        const uint32_t baseB = baseA + TILEB;                                     \
        _Pragma("unroll")                                                         \
        for (int kk2 = 0; kk2 < 2; kk2++) {  /* two k32 steps per 64B chunk */    \
            uint32_t af[2][4];                                                    \
            _Pragma("unroll")                                                     \
            for (int mf = 0; mf < 2; mf++) {                                      \
                uint32_t ad = baseA + (uint32_t)((aRow + mf * 16) * RSTRIDE       \
                                                 + kk2 * 32 + aKoff);             \
                asm volatile("ldmatrix.sync.aligned.m8n8.x4.shared.b16 "          \
                             "{%0,%1,%2,%3}, [%4];"                               \
                             : "=r"(af[mf][0]), "=r"(af[mf][1]),                  \
                               "=r"(af[mf][2]), "=r"(af[mf][3]) : "r"(ad));       \
            }                                                                     \
            uint32_t bfr[8][2];                                                   \
            _Pragma("unroll")                                                     \
            for (int nfp = 0; nfp < 4; nfp++) {                                   \
                uint32_t bd = baseB + (uint32_t)((bRow + nfp * 16) * RSTRIDE      \
                                                 + kk2 * 32 + bKoff);             \
                asm volatile("ldmatrix.sync.aligned.m8n8.x4.shared.b16 "          \
                             "{%0,%1,%2,%3}, [%4];"                               \
                             : "=r"(bfr[nfp*2][0]), "=r"(bfr[nfp*2][1]),          \
                               "=r"(bfr[nfp*2+1][0]), "=r"(bfr[nfp*2+1][1])       \
                             : "r"(bd));                                          \
            }                                                                     \
            _Pragma("unroll")                                                     \
            for (int mf = 0; mf < 2; mf++)                                        \
                _Pragma("unroll")                                                 \
                for (int nf = 0; nf < 8; nf++) {                                  \
                    asm volatile(                                                 \
                        "mma.sync.aligned.m16n8k32.row.col.f32.e4m3.e4m3.f32 "    \
                        "{%0,%1,%2,%3},{%4,%5,%6,%7},{%8,%9},{%0,%1,%2,%3};\n"    \
                        : "+f"(acc[mf][nf][0]), "+f"(acc[mf][nf][1]),             \
                          "+f"(acc[mf][nf][2]), "+f"(acc[mf][nf][3])              \
                        : "r"(af[mf][0]), "r"(af[mf][1]),                         \
                          "r"(af[mf][2]), "r"(af[mf][3]),                         \
                          "r"(bfr[nf][0]), "r"(bfr[nf][1]));                      \
                }                                                                 \
        }                                                                         \
    }

    asm volatile("cp.async.wait_group 3;" ::: "memory");
    __syncthreads();
    COMPUTE_CHUNK(0);
    asm volatile("cp.async.wait_group 2;" ::: "memory");
    __syncthreads();
    COMPUTE_CHUNK(1);
    asm volatile("cp.async.wait_group 1;" ::: "memory");
    __syncthreads();
    COMPUTE_CHUNK(2);
    asm volatile("cp.async.wait_group 0;" ::: "memory");
    __syncthreads();
    COMPUTE_CHUNK(3);

    // ---- diagonal exclusion ----
    if (bm == bn) {
        #pragma unroll
        for (int mf = 0; mf < 2; mf++)
            #pragma unroll
            for (int h = 0; h < 2; h++) {
                int lr = m0 + mf * 16 + qr + h * 8;
                #pragma unroll
                for (int nf = 0; nf < 8; nf++)
                    #pragma unroll
                    for (int e = 0; e < 2; e++) {
                        int lc = n0 + nf * 8 + qc * 2 + e;
                        if (lc == lr) acc[mf][nf][h * 2 + e] = -3.0f;
                    }
            }
    }

    // ---- row argmax ----
    #pragma unroll
    for (int mf = 0; mf < 2; mf++) {
        #pragma unroll
        for (int h = 0; h < 2; h++) {
            int gr = rowA + m0 + mf * 16 + qr + h * 8;
            float bv = -4.0f; int bc = rowB;
            #pragma unroll
            for (int nf = 0; nf < 8; nf++)
                #pragma unroll
                for (int e = 0; e < 2; e++) {
                    float v = acc[mf][nf][h * 2 + e];
                    if (v > bv) { bv = v; bc = rowB + n0 + nf * 8 + qc * 2 + e; }
                }
            #pragma unroll
            for (int o = 1; o < 4; o <<= 1) {
                float ov = __shfl_xor_sync(0xffffffffu, bv, o);
                int   oc = __shfl_xor_sync(0xffffffffu, bc, o);
                if (ov > bv) { bv = ov; bc = oc; }
            }
            if (qc == 0) {
                unsigned long long key =
                    ((unsigned long long)ordered_fp(bv) << 32) | (unsigned int)bc;
                atomicMax(&g_best[gr], key);
            }
        }
    }

    // ---- column argmax (mirrored tile) for off-diagonal tiles ----
    if (bn > bm) {
        float cbv[16]; int cbr[16];
        #pragma unroll
        for (int nf = 0; nf < 8; nf++)
            #pragma unroll
            for (int e = 0; e < 2; e++) {
                int id = nf * 2 + e;
                float bv = -4.0f; int br = rowA;
                #pragma unroll
                for (int mf = 0; mf < 2; mf++)
                    #pragma unroll
                    for (int h = 0; h < 2; h++) {
                        float v = acc[mf][nf][h * 2 + e];
                        if (v > bv) { bv = v; br = rowA + m0 + mf * 16 + qr + h * 8; }
                    }
                cbv[id] = bv; cbr[id] = br;
            }
        #pragma unroll
        for (int o = 4; o < 32; o <<= 1) {
            #pragma unroll
            for (int id = 0; id < 16; id++) {
                float ov = __shfl_xor_sync(0xffffffffu, cbv[id], o);
                int   orr = __shfl_xor_sync(0xffffffffu, cbr[id], o);
                if (ov > cbv[id]) { cbv[id] = ov; cbr[id] = orr; }
            }
        }
        if (qr == 0) {
            #pragma unroll
            for (int id = 0; id < 16; id++) {
                int gc = rowB + n0 + (id >> 1) * 8 + qc * 2 + (id & 1);
                unsigned long long key =
                    ((unsigned long long)ordered_fp(cbv[id]) << 32) | (unsigned int)cbr[id];
                atomicMax(&g_best[gc], key);
            }
        }
    }
}

// ---------------------------------------------------------------------------
// Kernel 3: exact fp32 distance from raw input + stored norms.
// ---------------------------------------------------------------------------
__global__ void koleo_final(const float* __restrict__ s, float* __restrict__ out, int Bn) {
    int warp = threadIdx.x >> 5, lane = threadIdx.x & 31;
    int row  = blockIdx.x * 8 + warp;
    int j    = (int)(g_best[row] & 0xffffffffull);
    float ni = g_norm[row], nj = g_norm[j];
    const float* xi = s + (size_t)row * D;
    const float* xj = s + (size_t)j * D;
    float acc = 0.f;
    #pragma unroll
    for (int k = lane; k < D; k += 32) {
        float d = xi[k] / ni - xj[k] / nj + 1e-8f;
        acc += d * d;
    }
    #pragma unroll
    for (int o = 16; o; o >>= 1) acc += __shfl_xor_sync(0xffffffffu, acc, o);
    if (lane == 0)
        atomicAdd(out, -logf(sqrtf(acc) + 1e-8f) / (float)Bn);
}

// ---------------------------------------------------------------------------
extern "C" void kernel_launch(void* const* d_in, const int* in_sizes, int n_in,
                              void* d_out, int out_size) {
    const float* student = (const float*)d_in[0];
    int B = in_sizes[0] / D / NCROPS;                 // 8192
    float* out = (float*)d_out;

    koleo_normalize<<<B / 8, 256>>>((const float4*)student, out);

    static int cfg_done = 0;
    if (!cfg_done) {
        cudaFuncSetAttribute(koleo_gemm_argmax,
                             cudaFuncAttributeMaxDynamicSharedMemorySize, SMEM_SZ);
        cfg_done = 1;
    }
    int T = B / 128;                                  // 64 tiles per side
    int ntiles = T * (T + 1) / 2;                     // 2080
    koleo_gemm_argmax<<<ntiles, 256, SMEM_SZ>>>(B);

    koleo_final<<<B / 8, 256>>>(student, out, B);
}